// round 13
// baseline (speedup 1.0000x reference)
#include <cuda_runtime.h>
#include <cuda_bf16.h>

#define Gg 4
#define NN 4096
#define NE 65536
#define NBES 8
#define CC 32
#define NBLK 444
#define NTHR 256
#define GT   (NBLK * NTHR)
#define NWARP (GT / 32)

// ---- scratch (static __device__, no allocation) ----
__device__ int    d_cnt[Gg * NN];       // zero at module load; re-zeroed in k_finalize
__device__ int    d_rowstart[Gg * NN];
__device__ int    d_cursor[Gg * NN];
__device__ int    d_srcA[Gg * NE];
__device__ float4 d_geom[Gg * NE * 4];  // per-edge CSR record: R[8], Y1[3], Y2[5]
__device__ float  d_hgath[(size_t)Gg * NE * CC];  // h gathered into CSR order (32MB)
__device__ float  d_h0[Gg * NN * CC];
__device__ float  d_h1[Gg * NN * CC];
__device__ float  d_gacc[Gg * 6];

#define PI_OVER_RC   0.5235987755982988f
#define SQRT_2_RC    0.5773502691896258f
#define SQ3F         1.7320508075688772f
#define SQRT15       3.872983346207417f
#define CY2_OVER_SQ6 1.1180339887498949f
#define CY2_OVER_SQ2 1.9364916731037085f
#define SQ2F         1.4142135623730951f
#define INV_SQ6      0.4082482904638631f
#define INV_SQ2      0.7071067811865475f
#define INV_SQ3      0.5773502691896258f

// K1: h0 = node_attr @ Wz ; histogram of dst ; zero gacc.
__global__ void k_init_hist(const float* __restrict__ na, const float* __restrict__ Wz,
                            const int* __restrict__ ei) {
    int idx = blockIdx.x * blockDim.x + threadIdx.x;
    if (idx < Gg * NN * CC) {
        int node = idx / CC;
        int c = idx & (CC - 1);
        const float* a = na + node * 3;
        d_h0[idx] = a[0] * Wz[c] + a[1] * Wz[CC + c] + a[2] * Wz[2 * CC + c];
    }
    if (idx < Gg * 6) d_gacc[idx] = 0.f;
    if (idx < Gg * NE) {
        int g = idx >> 16;
        int e = idx & (NE - 1);
        atomicAdd(&d_cnt[g * NN + ei[g * 2 * NE + NE + e]], 1);
    }
}

// K2: per-graph exclusive scan (block g handles graph g)
__global__ void k_scan() {
    __shared__ int ssc[NTHR];
    int g = blockIdx.x;
    int tid = threadIdx.x;
    int base = g * NN + tid * 16;
    int s = 0;
#pragma unroll
    for (int j = 0; j < 16; j++) s += d_cnt[base + j];
    ssc[tid] = s;
    __syncthreads();
    int val = s;
    for (int off = 1; off < NTHR; off <<= 1) {
        int xsh = (tid >= off) ? ssc[tid - off] : 0;
        __syncthreads();
        ssc[tid] += xsh;
        __syncthreads();
    }
    int run = ssc[tid] - val;
#pragma unroll
    for (int j = 0; j < 16; j++) {
        int idx = base + j;
        d_rowstart[idx] = run;
        d_cursor[idx] = run;
        run += d_cnt[idx];
    }
}

// K3: scatter + per-edge geometry (computed once, shared by both passes)
__global__ void k_scatter_geom(const int* __restrict__ ei,
                               const float* __restrict__ x,
                               const float* __restrict__ xv) {
    int idx = blockIdx.x * blockDim.x + threadIdx.x;
    if (idx >= Gg * NE) return;
    int g = idx >> 16;
    int e = idx & (NE - 1);
    int dst = ei[g * 2 * NE + NE + e];
    int src = ei[g * 2 * NE + e];
    int pos = atomicAdd(&d_cursor[g * NN + dst], 1);
    int p = g * NE + pos;
    d_srcA[p] = src;

    float r = x[g * NE + e];
    const float* v = xv + (g * NE + e) * 3;
    float vx = v[0], vy = v[1], vz = v[2];

    float Rr[8];
    {
        float theta = r * PI_OVER_RC;
        float s1, c1;
        __sincosf(theta, &s1, &c1);
        float tc = c1 + c1;
        float inv = (r > 1e-12f) ? (SQRT_2_RC / r) : 0.f;
        float sm1 = 0.f, sc = s1;
#pragma unroll
        for (int b = 0; b < 8; b++) {
            Rr[b] = sc * inv;
            float nx = tc * sc - sm1;
            sm1 = sc; sc = nx;
        }
        if (r <= 1e-12f) {
#pragma unroll
            for (int b = 0; b < 8; b++) Rr[b] = SQRT_2_RC * (b + 1) * PI_OVER_RC;
        }
    }

    float nv = sqrtf(vx * vx + vy * vy + vz * vz);
    float inu = 1.f / (nv + 1e-9f);
    float ux = vx * inu, uy = vy * inu, uz = vz * inu;
    float ux2 = ux * ux, uy2 = uy * uy, uz2 = uz * uz;

    float4* rec = d_geom + (size_t)p * 4;
    rec[0] = make_float4(Rr[0], Rr[1], Rr[2], Rr[3]);
    rec[1] = make_float4(Rr[4], Rr[5], Rr[6], Rr[7]);
    rec[2] = make_float4(SQ3F * ux, SQ3F * uy, SQ3F * uz, SQRT15 * ux * uy);
    rec[3] = make_float4(SQRT15 * uy * uz,
                         CY2_OVER_SQ6 * (2.f * uz2 - ux2 - uy2),
                         SQRT15 * ux * uz,
                         CY2_OVER_SQ2 * (ux2 - uy2));
}

// K-gather: hgath[p, c] = h[src[p], c]. Buffer selected in DEVICE code
// (a __device__ symbol must not be passed from host).
template <bool PASS1>
__global__ void k_gather() {
    int idx = blockIdx.x * blockDim.x + threadIdx.x;
    if (idx >= Gg * NE * CC) return;
    const float* hin = PASS1 ? d_h0 : d_h1;
    int p = idx >> 5;          // CSR position (warp-uniform)
    int lane = idx & 31;
    int g = p >> 16;
    int s = __ldg(&d_srcA[p]);
    d_hgath[idx] = hin[(g * NN + s) * CC + lane];
}

__device__ __forceinline__ void flush_acc(float* sacc, int g, int lane,
                                          float r0, float r1, float r2,
                                          float r3, float r4, float r5) {
#pragma unroll
    for (int off = 16; off; off >>= 1) {
        r0 += __shfl_xor_sync(0xffffffffu, r0, off);
        r1 += __shfl_xor_sync(0xffffffffu, r1, off);
        r2 += __shfl_xor_sync(0xffffffffu, r2, off);
        r3 += __shfl_xor_sync(0xffffffffu, r3, off);
        r4 += __shfl_xor_sync(0xffffffffu, r4, off);
        r5 += __shfl_xor_sync(0xffffffffu, r5, off);
    }
    if (lane == 0) {
        atomicAdd(&sacc[g * 6 + 0], r0);
        atomicAdd(&sacc[g * 6 + 1], r1);
        atomicAdd(&sacc[g * 6 + 2], r2);
        atomicAdd(&sacc[g * 6 + 3], r3);
        atomicAdd(&sacc[g * 6 + 4], r4);
        atomicAdd(&sacc[g * 6 + 5], r5);
    }
}

// K4/K5: fused message-pass + prod3body + readout (+ f0 update in pass1)
// Pure streaming inner loop: NO data-dependent addresses.
template <bool PASS1>
__global__ void __launch_bounds__(NTHR, 3)
k_pass(const float* __restrict__ Wrad, const float* __restrict__ Wp,
       const float* __restrict__ Wr0, const float* __restrict__ Wr2,
       const float* __restrict__ Wm0) {
    __shared__ float sWm0[CC * CC];
    __shared__ float sacc[Gg * 6];
    int tid = threadIdx.x;
    int lane = tid & 31;
    int gwarp = (blockIdx.x * NTHR + tid) >> 5;

    if (PASS1)
        for (int i = tid; i < CC * CC; i += NTHR) sWm0[i] = Wm0[i];
    if (tid < Gg * 6) sacc[tid] = 0.f;
    __syncthreads();

    float wr[NBES][3];
#pragma unroll
    for (int b = 0; b < NBES; b++) {
        wr[b][0] = Wrad[b * 96 + lane * 3 + 0];
        wr[b][1] = Wrad[b * 96 + lane * 3 + 1];
        wr[b][2] = Wrad[b * 96 + lane * 3 + 2];
    }
    float wp0 = Wp[lane], wp1 = Wp[CC + lane], wp2 = Wp[2 * CC + lane];
    float wp5 = Wp[5 * CC + lane], wp6 = Wp[6 * CC + lane];
    float wr0 = Wr0[lane], wr2v = Wr2[lane];

    int curg = -1;
    float r0 = 0.f, r1 = 0.f, r2 = 0.f, r3 = 0.f, r4 = 0.f, r5 = 0.f;

    for (int node = gwarp; node < Gg * NN; node += NWARP) {
        int g = node >> 12;
        if (g != curg) {
            if (curg >= 0) flush_acc(sacc, curg, lane, r0, r1, r2, r3, r4, r5);
            curg = g;
            r0 = r1 = r2 = r3 = r4 = r5 = 0.f;
        }
        int n = node & (NN - 1);
        int start = d_rowstart[g * NN + n];
        int deg = d_cnt[g * NN + n];
        int p = g * NE + start;
        const float4* rec = d_geom + (size_t)p * 4;
        const float* phg = d_hgath + (size_t)p * CC + lane;

        float a0 = 0.f, a1x = 0.f, a1y = 0.f, a1z = 0.f;
        float q0 = 0.f, q1 = 0.f, q2 = 0.f, q3 = 0.f, q4 = 0.f;

#pragma unroll 4
        for (int i = 0; i < deg; i++) {
            float hs = phg[i * CC];
            float4 Ra = rec[i * 4 + 0];
            float4 Rb = rec[i * 4 + 1];
            float4 Ya = rec[i * 4 + 2];
            float4 Yb = rec[i * 4 + 3];
            float w0 = Ra.x * wr[0][0] + Ra.y * wr[1][0] + Ra.z * wr[2][0] + Ra.w * wr[3][0]
                     + Rb.x * wr[4][0] + Rb.y * wr[5][0] + Rb.z * wr[6][0] + Rb.w * wr[7][0];
            float w1 = Ra.x * wr[0][1] + Ra.y * wr[1][1] + Ra.z * wr[2][1] + Ra.w * wr[3][1]
                     + Rb.x * wr[4][1] + Rb.y * wr[5][1] + Rb.z * wr[6][1] + Rb.w * wr[7][1];
            float w2 = Ra.x * wr[0][2] + Ra.y * wr[1][2] + Ra.z * wr[2][2] + Ra.w * wr[3][2]
                     + Rb.x * wr[4][2] + Rb.y * wr[5][2] + Rb.z * wr[6][2] + Rb.w * wr[7][2];
            float g0 = w0 * hs, g1 = w1 * hs, g2 = w2 * hs;
            a0 += g0;
            a1x += g1 * Ya.x; a1y += g1 * Ya.y; a1z += g1 * Ya.z;
            q0 += g2 * Ya.w;  q1 += g2 * Yb.x;  q2 += g2 * Yb.y;
            q3 += g2 * Yb.z;  q4 += g2 * Yb.w;
        }

        float d11 = a1x * a1x + a1y * a1y + a1z * a1z;
        float d22 = q0 * q0 + q1 * q1 + q2 * q2 + q3 * q3 + q4 * q4;
        float B0 = wp0 * a0 * a0 + wp1 * d11 + wp2 * d22;

        float t5a = SQ2F * a1x * a1y;
        float t5b = SQ2F * a1y * a1z;
        float t5c = (2.f * a1z * a1z - a1x * a1x - a1y * a1y) * INV_SQ6;
        float t5d = SQ2F * a1x * a1z;
        float t5e = (a1x * a1x - a1y * a1y) * INV_SQ2;
        float B2a = wp5 * a0 * q0 + wp6 * t5a;
        float B2b = wp5 * a0 * q1 + wp6 * t5b;
        float B2c = wp5 * a0 * q2 + wp6 * t5c;
        float B2d = wp5 * a0 * q3 + wp6 * t5d;
        float B2e = wp5 * a0 * q4 + wp6 * t5e;

        r0 += B0 * wr0;
        r1 += B2a * wr2v; r2 += B2b * wr2v; r3 += B2c * wr2v;
        r4 += B2d * wr2v; r5 += B2e * wr2v;

        if (PASS1) {
            float f = 0.f;
#pragma unroll
            for (int k = 0; k < 32; k++) {
                float bk = __shfl_sync(0xffffffffu, B0, k);
                f += bk * sWm0[k * CC + lane];
            }
            f = f / (1.f + __expf(-f));
            d_h1[(g * NN + n) * CC + lane] = f;
        }
    }
    if (curg >= 0) flush_acc(sacc, curg, lane, r0, r1, r2, r3, r4, r5);

    __syncthreads();
    if (tid < Gg * 6) atomicAdd(&d_gacc[tid], sacc[tid]);
}

// K6: finalize -> out[g]; also re-zero d_cnt for the next replay
__global__ void k_finalize(float* __restrict__ out) {
    int idx = blockIdx.x * blockDim.x + threadIdx.x;
    if (blockIdx.x == 0 && threadIdx.x < Gg) {
        int g = threadIdx.x;
        float s = d_gacc[g * 6 + 0];
        float a = d_gacc[g * 6 + 1];
        float b = d_gacc[g * 6 + 2];
        float c = d_gacc[g * 6 + 3];
        float d = d_gacc[g * 6 + 4];
        float e = d_gacc[g * 6 + 5];
        float diag = s * INV_SQ3;
        out[g * 9 + 0] = diag - c * INV_SQ6 + e * INV_SQ2;
        out[g * 9 + 1] = a * INV_SQ2;
        out[g * 9 + 2] = d * INV_SQ2;
        out[g * 9 + 3] = a * INV_SQ2;
        out[g * 9 + 4] = diag - c * INV_SQ6 - e * INV_SQ2;
        out[g * 9 + 5] = b * INV_SQ2;
        out[g * 9 + 6] = d * INV_SQ2;
        out[g * 9 + 7] = b * INV_SQ2;
        out[g * 9 + 8] = diag + 2.f * c * INV_SQ6;
    }
    if (idx < Gg * NN) d_cnt[idx] = 0;
}

extern "C" void kernel_launch(void* const* d_in, const int* in_sizes, int n_in,
                              void* d_out, int out_size) {
    const float* x     = (const float*)d_in[0];
    const float* xv    = (const float*)d_in[1];
    const float* na    = (const float*)d_in[2];
    const int*   ei    = (const int*)d_in[3];
    const float* Wz    = (const float*)d_in[4];
    const float* Wrad1 = (const float*)d_in[5];
    const float* Wrad2 = (const float*)d_in[6];
    const float* Wp    = (const float*)d_in[7];
    const float* Wr0_1 = (const float*)d_in[8];
    const float* Wr2_1 = (const float*)d_in[9];
    const float* Wm0   = (const float*)d_in[10];
    const float* Wr0_2 = (const float*)d_in[11];
    const float* Wr2_2 = (const float*)d_in[12];
    float* out = (float*)d_out;

    k_init_hist<<<(Gg * NN * CC + 255) / 256, 256>>>(na, Wz, ei);
    k_scan<<<Gg, NTHR>>>();
    k_scatter_geom<<<(Gg * NE + 255) / 256, 256>>>(ei, x, xv);
    k_gather<true><<<(Gg * NE * CC + 255) / 256, 256>>>();
    k_pass<true><<<NBLK, NTHR>>>(Wrad1, Wp, Wr0_1, Wr2_1, Wm0);
    k_gather<false><<<(Gg * NE * CC + 255) / 256, 256>>>();
    k_pass<false><<<NBLK, NTHR>>>(Wrad2, Wp, Wr0_2, Wr2_2, Wm0);
    k_finalize<<<(Gg * NN + 255) / 256, 256>>>(out);
}

// round 14
// speedup vs baseline: 1.6108x; 1.6108x over previous
#include <cuda_runtime.h>
#include <cuda_bf16.h>

#define Gg 4
#define NN 4096
#define NE 65536
#define NBES 8
#define CC 32
#define NBLK 296
#define NTHR 256
#define GT   (NBLK * NTHR)
#define NWARP (GT / 32)

// ---- scratch (static __device__, no allocation) ----
__device__ int    d_cnt[Gg * NN];       // zero at module load; re-zeroed in k_finalize
__device__ int    d_rowstart[Gg * NN];
__device__ int    d_cursor[Gg * NN];
__device__ int    d_srcA[Gg * NE];
__device__ float4 d_geom[Gg * NE * 4];  // per-edge CSR record: R[8], Y1[3], Y2[5]
__device__ float  d_h0[Gg * NN * CC];
__device__ float  d_h1[Gg * NN * CC];
__device__ float  d_gacc[Gg * 6];

#define PI_OVER_RC   0.5235987755982988f
#define SQRT_2_RC    0.5773502691896258f
#define SQ3F         1.7320508075688772f
#define SQRT15       3.872983346207417f
#define CY2_OVER_SQ6 1.1180339887498949f
#define CY2_OVER_SQ2 1.9364916731037085f
#define SQ2F         1.4142135623730951f
#define INV_SQ6      0.4082482904638631f
#define INV_SQ2      0.7071067811865475f
#define INV_SQ3      0.5773502691896258f

// K1: h0 = node_attr @ Wz ; histogram of dst ; zero gacc.
__global__ void k_init_hist(const float* __restrict__ na, const float* __restrict__ Wz,
                            const int* __restrict__ ei) {
    int idx = blockIdx.x * blockDim.x + threadIdx.x;
    if (idx < Gg * NN * CC) {
        int node = idx / CC;
        int c = idx & (CC - 1);
        const float* a = na + node * 3;
        d_h0[idx] = a[0] * Wz[c] + a[1] * Wz[CC + c] + a[2] * Wz[2 * CC + c];
    }
    if (idx < Gg * 6) d_gacc[idx] = 0.f;
    if (idx < Gg * NE) {
        int g = idx >> 16;
        int e = idx & (NE - 1);
        atomicAdd(&d_cnt[g * NN + ei[g * 2 * NE + NE + e]], 1);
    }
}

// K2: per-graph exclusive scan (block g handles graph g)
__global__ void k_scan() {
    __shared__ int ssc[NTHR];
    int g = blockIdx.x;
    int tid = threadIdx.x;
    int base = g * NN + tid * 16;
    int s = 0;
#pragma unroll
    for (int j = 0; j < 16; j++) s += d_cnt[base + j];
    ssc[tid] = s;
    __syncthreads();
    int val = s;
    for (int off = 1; off < NTHR; off <<= 1) {
        int xsh = (tid >= off) ? ssc[tid - off] : 0;
        __syncthreads();
        ssc[tid] += xsh;
        __syncthreads();
    }
    int run = ssc[tid] - val;
#pragma unroll
    for (int j = 0; j < 16; j++) {
        int idx = base + j;
        d_rowstart[idx] = run;
        d_cursor[idx] = run;
        run += d_cnt[idx];
    }
}

// K3: scatter + per-edge geometry (computed once, shared by both passes)
__global__ void k_scatter_geom(const int* __restrict__ ei,
                               const float* __restrict__ x,
                               const float* __restrict__ xv) {
    int idx = blockIdx.x * blockDim.x + threadIdx.x;
    if (idx >= Gg * NE) return;
    int g = idx >> 16;
    int e = idx & (NE - 1);
    int dst = ei[g * 2 * NE + NE + e];
    int src = ei[g * 2 * NE + e];
    int pos = atomicAdd(&d_cursor[g * NN + dst], 1);
    int p = g * NE + pos;
    d_srcA[p] = src;

    float r = x[g * NE + e];
    const float* v = xv + (g * NE + e) * 3;
    float vx = v[0], vy = v[1], vz = v[2];

    float Rr[8];
    {
        float theta = r * PI_OVER_RC;
        float s1, c1;
        __sincosf(theta, &s1, &c1);
        float tc = c1 + c1;
        float inv = (r > 1e-12f) ? (SQRT_2_RC / r) : 0.f;
        float sm1 = 0.f, sc = s1;
#pragma unroll
        for (int b = 0; b < 8; b++) {
            Rr[b] = sc * inv;
            float nx = tc * sc - sm1;
            sm1 = sc; sc = nx;
        }
        if (r <= 1e-12f) {
#pragma unroll
            for (int b = 0; b < 8; b++) Rr[b] = SQRT_2_RC * (b + 1) * PI_OVER_RC;
        }
    }

    float nv = sqrtf(vx * vx + vy * vy + vz * vz);
    float inu = 1.f / (nv + 1e-9f);
    float ux = vx * inu, uy = vy * inu, uz = vz * inu;
    float ux2 = ux * ux, uy2 = uy * uy, uz2 = uz * uz;

    float4* rec = d_geom + (size_t)p * 4;
    rec[0] = make_float4(Rr[0], Rr[1], Rr[2], Rr[3]);
    rec[1] = make_float4(Rr[4], Rr[5], Rr[6], Rr[7]);
    rec[2] = make_float4(SQ3F * ux, SQ3F * uy, SQ3F * uz, SQRT15 * ux * uy);
    rec[3] = make_float4(SQRT15 * uy * uz,
                         CY2_OVER_SQ6 * (2.f * uz2 - ux2 - uy2),
                         SQRT15 * ux * uz,
                         CY2_OVER_SQ2 * (ux2 - uy2));
}

__device__ __forceinline__ void flush_acc(float* sacc, int g, int lane,
                                          float r0, float r1, float r2,
                                          float r3, float r4, float r5) {
#pragma unroll
    for (int off = 16; off; off >>= 1) {
        r0 += __shfl_xor_sync(0xffffffffu, r0, off);
        r1 += __shfl_xor_sync(0xffffffffu, r1, off);
        r2 += __shfl_xor_sync(0xffffffffu, r2, off);
        r3 += __shfl_xor_sync(0xffffffffu, r3, off);
        r4 += __shfl_xor_sync(0xffffffffu, r4, off);
        r5 += __shfl_xor_sync(0xffffffffu, r5, off);
    }
    if (lane == 0) {
        atomicAdd(&sacc[g * 6 + 0], r0);
        atomicAdd(&sacc[g * 6 + 1], r1);
        atomicAdd(&sacc[g * 6 + 2], r2);
        atomicAdd(&sacc[g * 6 + 3], r3);
        atomicAdd(&sacc[g * 6 + 4], r4);
        atomicAdd(&sacc[g * 6 + 5], r5);
    }
}

// K4/K5: fused message-pass + prod3body + readout (+ f0 update in pass1)
// R8's simple fused loop; 128-reg budget + unroll 4 so ptxas pipelines loads.
template <bool PASS1>
__global__ void __launch_bounds__(NTHR, 2)
k_pass(const float* __restrict__ Wrad, const float* __restrict__ Wp,
       const float* __restrict__ Wr0, const float* __restrict__ Wr2,
       const float* __restrict__ Wm0) {
    __shared__ float sWm0[CC * CC];
    __shared__ float sacc[Gg * 6];
    int tid = threadIdx.x;
    int lane = tid & 31;
    int gwarp = (blockIdx.x * NTHR + tid) >> 5;

    if (PASS1)
        for (int i = tid; i < CC * CC; i += NTHR) sWm0[i] = Wm0[i];
    if (tid < Gg * 6) sacc[tid] = 0.f;
    __syncthreads();

    float wr[NBES][3];
#pragma unroll
    for (int b = 0; b < NBES; b++) {
        wr[b][0] = Wrad[b * 96 + lane * 3 + 0];
        wr[b][1] = Wrad[b * 96 + lane * 3 + 1];
        wr[b][2] = Wrad[b * 96 + lane * 3 + 2];
    }
    float wp0 = Wp[lane], wp1 = Wp[CC + lane], wp2 = Wp[2 * CC + lane];
    float wp5 = Wp[5 * CC + lane], wp6 = Wp[6 * CC + lane];
    float wr0 = Wr0[lane], wr2v = Wr2[lane];

    const float* hin = PASS1 ? d_h0 : d_h1;

    int curg = -1;
    float r0 = 0.f, r1 = 0.f, r2 = 0.f, r3 = 0.f, r4 = 0.f, r5 = 0.f;

    for (int node = gwarp; node < Gg * NN; node += NWARP) {
        int g = node >> 12;
        if (g != curg) {
            if (curg >= 0) flush_acc(sacc, curg, lane, r0, r1, r2, r3, r4, r5);
            curg = g;
            r0 = r1 = r2 = r3 = r4 = r5 = 0.f;
        }
        int n = node & (NN - 1);
        const float* hbase = hin + g * NN * CC + lane;
        int start = d_rowstart[g * NN + n];
        int deg = d_cnt[g * NN + n];
        int p = g * NE + start;
        const float4* rec = d_geom + (size_t)p * 4;
        const int* psrc = d_srcA + p;

        float a0 = 0.f, a1x = 0.f, a1y = 0.f, a1z = 0.f;
        float q0 = 0.f, q1 = 0.f, q2 = 0.f, q3 = 0.f, q4 = 0.f;

#pragma unroll 4
        for (int i = 0; i < deg; i++) {
            int src = psrc[i];
            float4 Ra = rec[i * 4 + 0];
            float4 Rb = rec[i * 4 + 1];
            float4 Ya = rec[i * 4 + 2];
            float4 Yb = rec[i * 4 + 3];
            float hs = hbase[src * CC];

            float w0 = Ra.x * wr[0][0] + Ra.y * wr[1][0] + Ra.z * wr[2][0] + Ra.w * wr[3][0]
                     + Rb.x * wr[4][0] + Rb.y * wr[5][0] + Rb.z * wr[6][0] + Rb.w * wr[7][0];
            float w1 = Ra.x * wr[0][1] + Ra.y * wr[1][1] + Ra.z * wr[2][1] + Ra.w * wr[3][1]
                     + Rb.x * wr[4][1] + Rb.y * wr[5][1] + Rb.z * wr[6][1] + Rb.w * wr[7][1];
            float w2 = Ra.x * wr[0][2] + Ra.y * wr[1][2] + Ra.z * wr[2][2] + Ra.w * wr[3][2]
                     + Rb.x * wr[4][2] + Rb.y * wr[5][2] + Rb.z * wr[6][2] + Rb.w * wr[7][2];
            float g0 = w0 * hs, g1 = w1 * hs, g2 = w2 * hs;
            a0 += g0;
            a1x += g1 * Ya.x; a1y += g1 * Ya.y; a1z += g1 * Ya.z;
            q0 += g2 * Ya.w;  q1 += g2 * Yb.x;  q2 += g2 * Yb.y;
            q3 += g2 * Yb.z;  q4 += g2 * Yb.w;
        }

        float d11 = a1x * a1x + a1y * a1y + a1z * a1z;
        float d22 = q0 * q0 + q1 * q1 + q2 * q2 + q3 * q3 + q4 * q4;
        float B0 = wp0 * a0 * a0 + wp1 * d11 + wp2 * d22;

        float t5a = SQ2F * a1x * a1y;
        float t5b = SQ2F * a1y * a1z;
        float t5c = (2.f * a1z * a1z - a1x * a1x - a1y * a1y) * INV_SQ6;
        float t5d = SQ2F * a1x * a1z;
        float t5e = (a1x * a1x - a1y * a1y) * INV_SQ2;
        float B2a = wp5 * a0 * q0 + wp6 * t5a;
        float B2b = wp5 * a0 * q1 + wp6 * t5b;
        float B2c = wp5 * a0 * q2 + wp6 * t5c;
        float B2d = wp5 * a0 * q3 + wp6 * t5d;
        float B2e = wp5 * a0 * q4 + wp6 * t5e;

        r0 += B0 * wr0;
        r1 += B2a * wr2v; r2 += B2b * wr2v; r3 += B2c * wr2v;
        r4 += B2d * wr2v; r5 += B2e * wr2v;

        if (PASS1) {
            float f = 0.f;
#pragma unroll
            for (int k = 0; k < 32; k++) {
                float bk = __shfl_sync(0xffffffffu, B0, k);
                f += bk * sWm0[k * CC + lane];
            }
            f = f / (1.f + __expf(-f));
            d_h1[(g * NN + n) * CC + lane] = f;
        }
    }
    if (curg >= 0) flush_acc(sacc, curg, lane, r0, r1, r2, r3, r4, r5);

    __syncthreads();
    if (tid < Gg * 6) atomicAdd(&d_gacc[tid], sacc[tid]);
}

// K6: finalize -> out[g]; also re-zero d_cnt for the next replay
__global__ void k_finalize(float* __restrict__ out) {
    int idx = blockIdx.x * blockDim.x + threadIdx.x;
    if (blockIdx.x == 0 && threadIdx.x < Gg) {
        int g = threadIdx.x;
        float s = d_gacc[g * 6 + 0];
        float a = d_gacc[g * 6 + 1];
        float b = d_gacc[g * 6 + 2];
        float c = d_gacc[g * 6 + 3];
        float d = d_gacc[g * 6 + 4];
        float e = d_gacc[g * 6 + 5];
        float diag = s * INV_SQ3;
        out[g * 9 + 0] = diag - c * INV_SQ6 + e * INV_SQ2;
        out[g * 9 + 1] = a * INV_SQ2;
        out[g * 9 + 2] = d * INV_SQ2;
        out[g * 9 + 3] = a * INV_SQ2;
        out[g * 9 + 4] = diag - c * INV_SQ6 - e * INV_SQ2;
        out[g * 9 + 5] = b * INV_SQ2;
        out[g * 9 + 6] = d * INV_SQ2;
        out[g * 9 + 7] = b * INV_SQ2;
        out[g * 9 + 8] = diag + 2.f * c * INV_SQ6;
    }
    if (idx < Gg * NN) d_cnt[idx] = 0;
}

extern "C" void kernel_launch(void* const* d_in, const int* in_sizes, int n_in,
                              void* d_out, int out_size) {
    const float* x     = (const float*)d_in[0];
    const float* xv    = (const float*)d_in[1];
    const float* na    = (const float*)d_in[2];
    const int*   ei    = (const int*)d_in[3];
    const float* Wz    = (const float*)d_in[4];
    const float* Wrad1 = (const float*)d_in[5];
    const float* Wrad2 = (const float*)d_in[6];
    const float* Wp    = (const float*)d_in[7];
    const float* Wr0_1 = (const float*)d_in[8];
    const float* Wr2_1 = (const float*)d_in[9];
    const float* Wm0   = (const float*)d_in[10];
    const float* Wr0_2 = (const float*)d_in[11];
    const float* Wr2_2 = (const float*)d_in[12];
    float* out = (float*)d_out;

    k_init_hist<<<(Gg * NN * CC + 255) / 256, 256>>>(na, Wz, ei);
    k_scan<<<Gg, NTHR>>>();
    k_scatter_geom<<<(Gg * NE + 255) / 256, 256>>>(ei, x, xv);
    k_pass<true><<<NBLK, NTHR>>>(Wrad1, Wp, Wr0_1, Wr2_1, Wm0);
    k_pass<false><<<NBLK, NTHR>>>(Wrad2, Wp, Wr0_2, Wr2_2, Wm0);
    k_finalize<<<(Gg * NN + 255) / 256, 256>>>(out);
}